// round 3
// baseline (speedup 1.0000x reference)
#include <cuda_runtime.h>
#include <cuda_bf16.h>
#include <cstdint>

#define DIVUP(a,b) (((a)+(b)-1)/(b))

static constexpr int NN = 100000;   // nodes
static constexpr int NE = 1600000;  // edges
static constexpr int CI = 512;      // in_channels
static constexpr int CH = 256;      // hidden
static constexpr int CO = 40;       // out_channels
static constexpr int CO_PAD = 64;   // padded out channels for GEMM2

// ---------------- scratch (static device globals; no allocation) ----------------
__device__ __align__(16) __nv_bfloat16 g_qw1[CH * CI];
__device__ __align__(16) __nv_bfloat16 g_qw2[CO_PAD * CH];
__device__ __align__(16) float g_h[(size_t)NN * CH];        // hidden activations (fp32)
__device__ __align__(16) float g_z[(size_t)NN * CO];        // pre-propagation logits
__device__ __align__(16) float g_accum[(size_t)NN * CO];    // propagation accumulator
__device__ float g_deg[NN];
__device__ float g_dinv[NN];
__device__ int   g_maxbits[4];   // 0:|x| 1:|w1| 2:|w2| 3:|h|   (float bits, all >=0)
__device__ float g_scales[8];    // 0:sx 1:sx*sw1 2:sw1 3:sw2 4:sh 5:sh*sw2

// Reference-exact quantization level: clip(round(x / scale), -128, 127)
__device__ __forceinline__ float qlevel(float x, float s) {
    float q = rintf(__fdiv_rn(x, s));          // IEEE div + round-half-even (matches jnp)
    return fminf(fmaxf(q, -128.0f), 127.0f);
}

// ---------------- init ----------------
__global__ void zero_kernel() {
    size_t i = (size_t)blockIdx.x * blockDim.x + threadIdx.x;
    if (i < (size_t)NN * CO) g_accum[i] = 0.0f;
    if (i < NN) g_deg[i] = 0.0f;
    if (i < 4) g_maxbits[i] = 0;
}

// ---------------- abs-max reduction (float4, n divisible by 4) ----------------
__global__ void absmax_kernel(const float* __restrict__ p, size_t n4, int slot) {
    float m = 0.0f;
    size_t stride = (size_t)gridDim.x * blockDim.x;
    for (size_t i = (size_t)blockIdx.x * blockDim.x + threadIdx.x; i < n4; i += stride) {
        float4 v = reinterpret_cast<const float4*>(p)[i];
        m = fmaxf(m, fmaxf(fmaxf(fabsf(v.x), fabsf(v.y)), fmaxf(fabsf(v.z), fabsf(v.w))));
    }
    #pragma unroll
    for (int o = 16; o > 0; o >>= 1) m = fmaxf(m, __shfl_xor_sync(0xffffffffu, m, o));
    if ((threadIdx.x & 31) == 0) atomicMax(&g_maxbits[slot], __float_as_int(m));
}

__global__ void finalize1_kernel() {
    float sx  = __int_as_float(g_maxbits[0]) / 127.0f + 1e-12f;
    float sw1 = __int_as_float(g_maxbits[1]) / 127.0f + 1e-12f;
    float sw2 = __int_as_float(g_maxbits[2]) / 127.0f + 1e-12f;
    g_scales[0] = sx; g_scales[1] = sx * sw1; g_scales[2] = sw1; g_scales[3] = sw2;
}
__global__ void finalize2_kernel() {
    float sh = __int_as_float(g_maxbits[3]) / 127.0f + 1e-12f;
    g_scales[4] = sh; g_scales[5] = sh * g_scales[3];
}

// ---------------- weight quantization to bf16 integer levels ----------------
__global__ void quant_w1_kernel(const float* __restrict__ w) {
    int i = blockIdx.x * blockDim.x + threadIdx.x;
    if (i < CH * CI) g_qw1[i] = __float2bfloat16_rn(qlevel(w[i], g_scales[2]));
}
__global__ void quant_w2_kernel(const float* __restrict__ w) {
    int i = blockIdx.x * blockDim.x + threadIdx.x;
    if (i < CO_PAD * CH) {
        int r = i / CH, c = i % CH;
        float v = (r < CO) ? qlevel(w[r * CH + c], g_scales[3]) : 0.0f;
        g_qw2[i] = __float2bfloat16_rn(v);
    }
}

// ---------------- bf16 tensor-core GEMM: Out = quant(A) @ Bq^T * cs + bias ----------------
// A: fp32 [M,K] (quantized on the fly with g_scales[s_a]); Bq: bf16 int levels [*,K] row-major.
// Block: 256 threads = 8 warps; warp tile WMxWN via m16n8k16.
template<int BM, int BN, int WM, int WN, bool RELU, bool RECMAX>
__device__ __forceinline__ void gemm_device(
    const float* __restrict__ A, const __nv_bfloat16* __restrict__ Bq,
    const float* __restrict__ bias, float* __restrict__ Out,
    int M, int K, int NOUT, int s_a, int s_c, int maxslot)
{
    constexpr int BK = 32;
    constexpr int LDS = BK + 8;          // 40 bf16 = 80B rows: conflict-free & 16B-aligned
    __shared__ __nv_bfloat16 As[BM][LDS];
    __shared__ __nv_bfloat16 Bs[BN][LDS];

    const int tid = threadIdx.x;
    const int warp = tid >> 5;
    const int lane = tid & 31;
    constexpr int WARPS_N = BN / WN;
    const int wm = (warp / WARPS_N) * WM;
    const int wn = (warp % WARPS_N) * WN;
    constexpr int FM = WM / 16, FN = WN / 8;

    const int m0 = blockIdx.x * BM;
    const float scale_a = g_scales[s_a];

    float acc[FM][FN][4];
    #pragma unroll
    for (int a = 0; a < FM; a++)
        #pragma unroll
        for (int b = 0; b < FN; b++)
            #pragma unroll
            for (int c = 0; c < 4; c++) acc[a][b][c] = 0.0f;

    const int nk = K / BK;
    for (int kt = 0; kt < nk; kt++) {
        const int k0 = kt * BK;
        // --- load + quantize A tile: BM x 32 fp32 -> bf16 levels ---
        #pragma unroll
        for (int i = 0; i < BM * 8 / 256; i++) {
            int idx = tid + i * 256;
            int r = idx >> 3, c4 = (idx & 7) * 4;
            int gr = m0 + r;
            float4 v = make_float4(0.f, 0.f, 0.f, 0.f);
            if (gr < M) v = *reinterpret_cast<const float4*>(A + (size_t)gr * K + k0 + c4);
            float q0 = qlevel(v.x, scale_a), q1 = qlevel(v.y, scale_a);
            float q2 = qlevel(v.z, scale_a), q3 = qlevel(v.w, scale_a);
            __nv_bfloat162* p = reinterpret_cast<__nv_bfloat162*>(&As[r][c4]);
            p[0] = __floats2bfloat162_rn(q0, q1);
            p[1] = __floats2bfloat162_rn(q2, q3);
        }
        // --- load B tile: BN x 32 bf16 (already quantized) ---
        #pragma unroll
        for (int i = 0; i < BN * 4 / 256; i++) {
            int idx = tid + i * 256;
            int r = idx >> 2, seg = (idx & 3) * 8;
            uint4 v = *reinterpret_cast<const uint4*>(Bq + (size_t)r * K + k0 + seg);
            *reinterpret_cast<uint4*>(&Bs[r][seg]) = v;
        }
        __syncthreads();

        #pragma unroll
        for (int ks = 0; ks < 2; ks++) {
            unsigned af[FM][4], bf[FN][2];
            #pragma unroll
            for (int fm = 0; fm < FM; fm++) {
                unsigned addr = (unsigned)__cvta_generic_to_shared(
                    &As[wm + fm * 16 + (lane & 15)][ks * 16 + (lane >> 4) * 8]);
                asm volatile("ldmatrix.sync.aligned.m8n8.x4.shared.b16 {%0,%1,%2,%3}, [%4];"
                    : "=r"(af[fm][0]), "=r"(af[fm][1]), "=r"(af[fm][2]), "=r"(af[fm][3])
                    : "r"(addr));
            }
            #pragma unroll
            for (int fn = 0; fn < FN; fn++) {
                unsigned addr = (unsigned)__cvta_generic_to_shared(
                    &Bs[wn + fn * 8 + (lane & 7)][ks * 16 + ((lane >> 3) & 1) * 8]);
                asm volatile("ldmatrix.sync.aligned.m8n8.x2.shared.b16 {%0,%1}, [%2];"
                    : "=r"(bf[fn][0]), "=r"(bf[fn][1]) : "r"(addr));
            }
            #pragma unroll
            for (int fm = 0; fm < FM; fm++)
                #pragma unroll
                for (int fn = 0; fn < FN; fn++) {
                    asm volatile(
                        "mma.sync.aligned.m16n8k16.row.col.f32.bf16.bf16.f32 "
                        "{%0,%1,%2,%3},{%4,%5,%6,%7},{%8,%9},{%0,%1,%2,%3};"
                        : "+f"(acc[fm][fn][0]), "+f"(acc[fm][fn][1]),
                          "+f"(acc[fm][fn][2]), "+f"(acc[fm][fn][3])
                        : "r"(af[fm][0]), "r"(af[fm][1]), "r"(af[fm][2]), "r"(af[fm][3]),
                          "r"(bf[fn][0]), "r"(bf[fn][1]));
                }
        }
        __syncthreads();
    }

    // --- epilogue: scale + bias (+ relu, + |max| record) ---
    const float cs = g_scales[s_c];
    float lmax = 0.0f;
    #pragma unroll
    for (int fm = 0; fm < FM; fm++)
        #pragma unroll
        for (int fn = 0; fn < FN; fn++) {
            int col = wn + fn * 8 + (lane & 3) * 2;
            #pragma unroll
            for (int hh = 0; hh < 2; hh++) {
                int gr = m0 + wm + fm * 16 + (lane >> 2) + hh * 8;
                if (gr < M) {
                    #pragma unroll
                    for (int j = 0; j < 2; j++) {
                        int gc = col + j;
                        if (gc < NOUT) {
                            float v = acc[fm][fn][hh * 2 + j] * cs + bias[gc];
                            if (RELU) v = fmaxf(v, 0.0f);
                            Out[(size_t)gr * NOUT + gc] = v;
                            if (RECMAX) lmax = fmaxf(lmax, fabsf(v));
                        }
                    }
                }
            }
        }
    if (RECMAX) {
        #pragma unroll
        for (int o = 16; o > 0; o >>= 1) lmax = fmaxf(lmax, __shfl_xor_sync(0xffffffffu, lmax, o));
        if (lane == 0) atomicMax(&g_maxbits[maxslot], __float_as_int(lmax));
    }
}

__global__ void __launch_bounds__(256) gemm1_kernel(const float* __restrict__ x,
                                                    const float* __restrict__ b1) {
    gemm_device<64, 256, 32, 64, true, true>(x, g_qw1, b1, g_h, NN, CI, CH, 0, 1, 3);
}
__global__ void __launch_bounds__(256) gemm2_kernel(const float* __restrict__ b2) {
    gemm_device<128, 64, 32, 32, false, false>(g_h, g_qw2, b2, g_z, NN, CH, CO, 4, 5, -1);
}

// ---------------- graph propagation ----------------
__global__ void degree_kernel(const int* __restrict__ ei) {
    int e = blockIdx.x * blockDim.x + threadIdx.x;
    if (e < NE) atomicAdd(&g_deg[ei[NE + e]], 1.0f);
}
__global__ void dinv_kernel() {
    int i = blockIdx.x * blockDim.x + threadIdx.x;
    if (i < NN) {
        float d = g_deg[i];
        g_dinv[i] = (d > 0.0f) ? rsqrtf(fmaxf(d, 1.0f)) : 0.0f;
    }
}
// one thread per (edge, float4-chunk): 10 chunks cover 40 channels
__global__ void propagate_kernel(const int* __restrict__ ei) {
    int idx = blockIdx.x * blockDim.x + threadIdx.x;
    if (idx >= NE * 10) return;
    int e = idx / 10, ch = idx - e * 10;
    int src = ei[e], dst = ei[NE + e];
    float coef = g_dinv[src] * g_dinv[dst];
    float4 v = *reinterpret_cast<const float4*>(g_z + (size_t)src * CO + ch * 4);
    float* p = g_accum + (size_t)dst * CO + ch * 4;
    asm volatile("red.global.add.v4.f32 [%0], {%1,%2,%3,%4};"
                 :: "l"(p), "f"(v.x * coef), "f"(v.y * coef), "f"(v.z * coef), "f"(v.w * coef)
                 : "memory");
}

// ---------------- log-softmax (warp per node row of 40) ----------------
__global__ void logsoftmax_kernel(float* __restrict__ out) {
    int gw = (blockIdx.x * blockDim.x + threadIdx.x) >> 5;
    int lane = threadIdx.x & 31;
    if (gw >= NN) return;
    const float* row = g_accum + (size_t)gw * CO;
    float x1 = row[lane];
    float x2 = (lane < 8) ? row[32 + lane] : -3.402823466e+38f;
    float m = fmaxf(x1, x2);
    #pragma unroll
    for (int o = 16; o > 0; o >>= 1) m = fmaxf(m, __shfl_xor_sync(0xffffffffu, m, o));
    float s = expf(x1 - m) + ((lane < 8) ? expf(x2 - m) : 0.0f);
    #pragma unroll
    for (int o = 16; o > 0; o >>= 1) s += __shfl_xor_sync(0xffffffffu, s, o);
    float lse = m + logf(s);
    float* o = out + (size_t)gw * CO;
    o[lane] = x1 - lse;
    if (lane < 8) o[32 + lane] = x2 - lse;
}

// ---------------- launch ----------------
extern "C" void kernel_launch(void* const* d_in, const int* in_sizes, int n_in,
                              void* d_out, int out_size) {
    const float* x  = (const float*)d_in[0];
    const int*   ei = (const int*)d_in[1];
    const float* w1 = (const float*)d_in[2];
    const float* b1 = (const float*)d_in[3];
    const float* w2 = (const float*)d_in[4];
    const float* b2 = (const float*)d_in[5];
    float* out = (float*)d_out;

    zero_kernel<<<DIVUP((size_t)NN * CO, 256), 256>>>();

    absmax_kernel<<<2048, 256>>>(x,  (size_t)NN * CI / 4, 0);
    absmax_kernel<<<128,  256>>>(w1, (size_t)CH * CI / 4, 1);
    absmax_kernel<<<10,   256>>>(w2, (size_t)CO * CH / 4, 2);
    finalize1_kernel<<<1, 1>>>();

    quant_w1_kernel<<<DIVUP(CH * CI, 256), 256>>>(w1);
    quant_w2_kernel<<<DIVUP(CO_PAD * CH, 256), 256>>>(w2);

    gemm1_kernel<<<DIVUP(NN, 64), 256>>>(x, b1);     // h = relu(fq(x) @ fq(w1)^T), records max|h|
    finalize2_kernel<<<1, 1>>>();
    gemm2_kernel<<<DIVUP(NN, 128), 256>>>(b2);       // z = fq(h) @ fq(w2)^T

    degree_kernel<<<DIVUP(NE, 256), 256>>>(ei);
    dinv_kernel<<<DIVUP(NN, 256), 256>>>();
    propagate_kernel<<<DIVUP(NE * 10, 256), 256>>>(ei);

    logsoftmax_kernel<<<DIVUP(NN * 32, 256), 256>>>(out);
}

// round 4
// speedup vs baseline: 1.4802x; 1.4802x over previous
#include <cuda_runtime.h>
#include <cuda_bf16.h>
#include <cstdint>

#define DIVUP(a,b) (((a)+(b)-1)/(b))

static constexpr int NN = 100000;   // nodes
static constexpr int NE = 1600000;  // edges
static constexpr int CI = 512;      // in_channels
static constexpr int CH = 256;      // hidden
static constexpr int CO = 40;       // out_channels
static constexpr int CO_PAD = 64;   // padded out channels for GEMM2

// ---------------- scratch (static device globals; no allocation) ----------------
__device__ __align__(16) __nv_bfloat16 g_qw1[CH * CI];
__device__ __align__(16) __nv_bfloat16 g_qw2[CO_PAD * CH];
__device__ __align__(16) __nv_bfloat16 g_h[(size_t)NN * CH];  // hidden activations (bf16)
__device__ __align__(16) float g_z[(size_t)NN * CO];          // pre-propagation logits
__device__ __align__(16) float g_accum[(size_t)NN * CO];      // propagation accumulator
__device__ float g_deg[NN];
__device__ float g_dinv[NN];
__device__ int   g_maxbits[4];   // 0:|x| 1:|w1| 2:|w2| 3:|h|   (float bits, all >=0)
// scales: 0:1/sx 1:sx*sw1 2:1/sw1 3:1/sw2 4:1/sh 5:sh*sw2 6:sw2
__device__ float g_scales[8];

__device__ __forceinline__ float qlevel_mul(float x, float inv) {
    float q = rintf(x * inv);
    return fminf(fmaxf(q, -128.0f), 127.0f);
}

// ---------------- init ----------------
__global__ void zero_kernel() {
    int i = blockIdx.x * blockDim.x + threadIdx.x;
    if (i < NN * CO / 4) reinterpret_cast<float4*>(g_accum)[i] = make_float4(0.f,0.f,0.f,0.f);
    if (i < NN) g_deg[i] = 0.0f;
    if (i < 4) g_maxbits[i] = 0;
}

// ---------------- abs-max reduction (float4, n divisible by 4) ----------------
__global__ void absmax_kernel(const float* __restrict__ p, size_t n4, int slot) {
    float m = 0.0f;
    size_t stride = (size_t)gridDim.x * blockDim.x;
    #pragma unroll 4
    for (size_t i = (size_t)blockIdx.x * blockDim.x + threadIdx.x; i < n4; i += stride) {
        float4 v = reinterpret_cast<const float4*>(p)[i];
        m = fmaxf(m, fmaxf(fmaxf(fabsf(v.x), fabsf(v.y)), fmaxf(fabsf(v.z), fabsf(v.w))));
    }
    #pragma unroll
    for (int o = 16; o > 0; o >>= 1) m = fmaxf(m, __shfl_xor_sync(0xffffffffu, m, o));
    if ((threadIdx.x & 31) == 0) atomicMax(&g_maxbits[slot], __float_as_int(m));
}

__global__ void finalize1_kernel() {
    float sx  = __int_as_float(g_maxbits[0]) / 127.0f + 1e-12f;
    float sw1 = __int_as_float(g_maxbits[1]) / 127.0f + 1e-12f;
    float sw2 = __int_as_float(g_maxbits[2]) / 127.0f + 1e-12f;
    g_scales[0] = 1.0f / sx;
    g_scales[1] = sx * sw1;
    g_scales[2] = 1.0f / sw1;
    g_scales[3] = 1.0f / sw2;
    g_scales[6] = sw2;
}
__global__ void finalize2_kernel() {
    float sh = __int_as_float(g_maxbits[3]) / 127.0f + 1e-12f;
    g_scales[4] = 1.0f / sh;
    g_scales[5] = sh * g_scales[6];
}

// ---------------- weight quantization to bf16 integer levels ----------------
__global__ void quant_w1_kernel(const float* __restrict__ w) {
    int i = blockIdx.x * blockDim.x + threadIdx.x;
    if (i < CH * CI) g_qw1[i] = __float2bfloat16_rn(qlevel_mul(w[i], g_scales[2]));
}
__global__ void quant_w2_kernel(const float* __restrict__ w) {
    int i = blockIdx.x * blockDim.x + threadIdx.x;
    if (i < CO_PAD * CH) {
        int r = i / CH, c = i % CH;
        float v = (r < CO) ? qlevel_mul(w[r * CH + c], g_scales[3]) : 0.0f;
        g_qw2[i] = __float2bfloat16_rn(v);
    }
}

// ---------------- pipelined bf16 tensor-core GEMM ----------------
// Out = quant(A) @ Bq^T * cs + bias; A fp32 or bf16 [M,K] quantized on the fly,
// Bq bf16 integer levels [*,K] row-major. 256 threads, BK=64, double-buffered
// smem, cp.async for B, register prefetch for A, one __syncthreads per k-iter.
template<int BM, int BN, int WM, int WN, bool RELU, bool RECMAX, bool A_BF16, bool OUT_BF16>
__device__ __forceinline__ void gemm_pipe(
    const void* __restrict__ Avoid, const __nv_bfloat16* __restrict__ Bq,
    const float* __restrict__ bias, void* __restrict__ Outv,
    int M, int K, int NOUT, int s_inv_a, int s_c, int maxslot)
{
    constexpr int BK = 64;
    constexpr int LDS = BK + 8;            // 72 bf16 = 144B rows (16B-aligned, conflict-free)
    extern __shared__ __align__(16) char smem_raw[];
    __nv_bfloat16* As = reinterpret_cast<__nv_bfloat16*>(smem_raw);   // [2][BM][LDS]
    __nv_bfloat16* Bs = As + 2 * BM * LDS;                             // [2][BN][LDS]

    const int tid = threadIdx.x, warp = tid >> 5, lane = tid & 31;
    constexpr int WARPS_N = BN / WN;
    const int wm = (warp / WARPS_N) * WM;
    const int wn = (warp % WARPS_N) * WN;
    constexpr int FM = WM / 16, FN = WN / 8;
    const int m0 = blockIdx.x * BM;
    const float inv_a = g_scales[s_inv_a];

    constexpr int A_VECS = BM * BK / (256 * (A_BF16 ? 8 : 4));
    constexpr int B_VECS = BN * BK / (256 * 8);

    float4 aregf[A_BF16 ? 1 : A_VECS];
    uint4  aregh[A_BF16 ? A_VECS : 1];

    float acc[FM][FN][4];
    #pragma unroll
    for (int a = 0; a < FM; a++)
        #pragma unroll
        for (int b = 0; b < FN; b++)
            #pragma unroll
            for (int c = 0; c < 4; c++) acc[a][b][c] = 0.0f;

    auto loadA = [&](int k0) {
        if constexpr (!A_BF16) {
            const float* A = (const float*)Avoid;
            #pragma unroll
            for (int i = 0; i < A_VECS; i++) {
                int idx = tid + i * 256, r = idx >> 4, c = (idx & 15) << 2, gr = m0 + r;
                aregf[i] = (gr < M) ? *reinterpret_cast<const float4*>(A + (size_t)gr * K + k0 + c)
                                    : make_float4(0.f, 0.f, 0.f, 0.f);
            }
        } else {
            const __nv_bfloat16* A = (const __nv_bfloat16*)Avoid;
            #pragma unroll
            for (int i = 0; i < A_VECS; i++) {
                int idx = tid + i * 256, r = idx >> 3, c = (idx & 7) << 3, gr = m0 + r;
                aregh[i] = (gr < M) ? *reinterpret_cast<const uint4*>(A + (size_t)gr * K + k0 + c)
                                    : make_uint4(0u, 0u, 0u, 0u);
            }
        }
    };
    auto storeA = [&](int buf) {
        __nv_bfloat16* base = As + buf * BM * LDS;
        if constexpr (!A_BF16) {
            #pragma unroll
            for (int i = 0; i < A_VECS; i++) {
                int idx = tid + i * 256, r = idx >> 4, c = (idx & 15) << 2;
                float4 v = aregf[i];
                __nv_bfloat162* p = reinterpret_cast<__nv_bfloat162*>(base + r * LDS + c);
                p[0] = __floats2bfloat162_rn(qlevel_mul(v.x, inv_a), qlevel_mul(v.y, inv_a));
                p[1] = __floats2bfloat162_rn(qlevel_mul(v.z, inv_a), qlevel_mul(v.w, inv_a));
            }
        } else {
            #pragma unroll
            for (int i = 0; i < A_VECS; i++) {
                int idx = tid + i * 256, r = idx >> 3, c = (idx & 7) << 3;
                uint4 u = aregh[i];
                uint4 o;
                const __nv_bfloat162* hi = reinterpret_cast<const __nv_bfloat162*>(&u);
                __nv_bfloat162* ho = reinterpret_cast<__nv_bfloat162*>(&o);
                #pragma unroll
                for (int j = 0; j < 4; j++) {
                    float2 f = __bfloat1622float2(hi[j]);
                    ho[j] = __floats2bfloat162_rn(qlevel_mul(f.x, inv_a), qlevel_mul(f.y, inv_a));
                }
                *reinterpret_cast<uint4*>(base + r * LDS + c) = o;
            }
        }
    };
    auto cpB = [&](int k0, int buf) {
        #pragma unroll
        for (int i = 0; i < B_VECS; i++) {
            int idx = tid + i * 256, r = idx >> 3, c = (idx & 7) << 3;
            unsigned d = (unsigned)__cvta_generic_to_shared(Bs + (buf * BN + r) * LDS + c);
            const __nv_bfloat16* g = Bq + (size_t)r * K + k0 + c;
            asm volatile("cp.async.cg.shared.global [%0], [%1], 16;\n" :: "r"(d), "l"(g));
        }
    };

    const int nk = K / BK;
    // prologue
    loadA(0);
    cpB(0, 0);
    asm volatile("cp.async.commit_group;\n");

    for (int kt = 0; kt < nk; kt++) {
        const int cur = kt & 1;
        storeA(cur);                               // quantize prev-loaded A regs into smem
        asm volatile("cp.async.wait_group 0;\n");  // B(kt) arrived
        __syncthreads();
        if (kt + 1 < nk) {                         // prefetch next tile (overlaps mma below)
            loadA((kt + 1) * BK);
            cpB((kt + 1) * BK, cur ^ 1);
        }
        asm volatile("cp.async.commit_group;\n");

        const __nv_bfloat16* Ab = As + cur * BM * LDS;
        const __nv_bfloat16* Bb = Bs + cur * BN * LDS;
        #pragma unroll
        for (int ks = 0; ks < BK / 16; ks++) {
            unsigned af[FM][4], bf[FN][2];
            #pragma unroll
            for (int fm = 0; fm < FM; fm++) {
                unsigned addr = (unsigned)__cvta_generic_to_shared(
                    Ab + (wm + fm * 16 + (lane & 15)) * LDS + ks * 16 + (lane >> 4) * 8);
                asm volatile("ldmatrix.sync.aligned.m8n8.x4.shared.b16 {%0,%1,%2,%3}, [%4];"
                    : "=r"(af[fm][0]), "=r"(af[fm][1]), "=r"(af[fm][2]), "=r"(af[fm][3])
                    : "r"(addr));
            }
            #pragma unroll
            for (int fn = 0; fn < FN; fn++) {
                unsigned addr = (unsigned)__cvta_generic_to_shared(
                    Bb + (wn + fn * 8 + (lane & 7)) * LDS + ks * 16 + ((lane >> 3) & 1) * 8);
                asm volatile("ldmatrix.sync.aligned.m8n8.x2.shared.b16 {%0,%1}, [%2];"
                    : "=r"(bf[fn][0]), "=r"(bf[fn][1]) : "r"(addr));
            }
            #pragma unroll
            for (int fm = 0; fm < FM; fm++)
                #pragma unroll
                for (int fn = 0; fn < FN; fn++) {
                    asm volatile(
                        "mma.sync.aligned.m16n8k16.row.col.f32.bf16.bf16.f32 "
                        "{%0,%1,%2,%3},{%4,%5,%6,%7},{%8,%9},{%0,%1,%2,%3};"
                        : "+f"(acc[fm][fn][0]), "+f"(acc[fm][fn][1]),
                          "+f"(acc[fm][fn][2]), "+f"(acc[fm][fn][3])
                        : "r"(af[fm][0]), "r"(af[fm][1]), "r"(af[fm][2]), "r"(af[fm][3]),
                          "r"(bf[fn][0]), "r"(bf[fn][1]));
                }
        }
    }

    // --- epilogue: scale + bias (+ relu, + |max| record) ---
    const float cs = g_scales[s_c];
    float lmax = 0.0f;
    #pragma unroll
    for (int fm = 0; fm < FM; fm++)
        #pragma unroll
        for (int fn = 0; fn < FN; fn++) {
            int col = wn + fn * 8 + (lane & 3) * 2;
            #pragma unroll
            for (int hh = 0; hh < 2; hh++) {
                int gr = m0 + wm + fm * 16 + (lane >> 2) + hh * 8;
                if (gr < M) {
                    if constexpr (OUT_BF16) {
                        float v0 = acc[fm][fn][hh * 2 + 0] * cs + bias[col];
                        float v1 = acc[fm][fn][hh * 2 + 1] * cs + bias[col + 1];
                        if (RELU) { v0 = fmaxf(v0, 0.0f); v1 = fmaxf(v1, 0.0f); }
                        if (RECMAX) lmax = fmaxf(lmax, fmaxf(fabsf(v0), fabsf(v1)));
                        *reinterpret_cast<__nv_bfloat162*>(
                            (__nv_bfloat16*)Outv + (size_t)gr * NOUT + col) =
                            __floats2bfloat162_rn(v0, v1);
                    } else {
                        #pragma unroll
                        for (int j = 0; j < 2; j++) {
                            int gc = col + j;
                            if (gc < NOUT) {
                                float v = acc[fm][fn][hh * 2 + j] * cs + bias[gc];
                                if (RELU) v = fmaxf(v, 0.0f);
                                if (RECMAX) lmax = fmaxf(lmax, fabsf(v));
                                ((float*)Outv)[(size_t)gr * NOUT + gc] = v;
                            }
                        }
                    }
                }
            }
        }
    if (RECMAX) {
        #pragma unroll
        for (int o = 16; o > 0; o >>= 1) lmax = fmaxf(lmax, __shfl_xor_sync(0xffffffffu, lmax, o));
        if (lane == 0) atomicMax(&g_maxbits[maxslot], __float_as_int(lmax));
    }
}

static constexpr int LDSC = 72;
static constexpr int SMEM1 = 2 * (64 + 256) * LDSC * 2;   // 92160 B
static constexpr int SMEM2 = 2 * (128 + 64) * LDSC * 2;   // 55296 B

__global__ void __launch_bounds__(256) gemm1_kernel(const float* __restrict__ x,
                                                    const float* __restrict__ b1) {
    gemm_pipe<64, 256, 32, 64, true, true, false, true>(
        x, g_qw1, b1, g_h, NN, CI, CH, 0, 1, 3);
}
__global__ void __launch_bounds__(256) gemm2_kernel(const float* __restrict__ b2) {
    gemm_pipe<128, 64, 32, 32, false, false, true, false>(
        g_h, g_qw2, b2, g_z, NN, CH, CO, 4, 5, -1);
}

// ---------------- graph propagation ----------------
__global__ void degree_kernel(const int* __restrict__ ei) {
    int e = blockIdx.x * blockDim.x + threadIdx.x;
    if (e < NE) atomicAdd(&g_deg[ei[NE + e]], 1.0f);
}
__global__ void dinv_kernel() {
    int i = blockIdx.x * blockDim.x + threadIdx.x;
    if (i < NN) {
        float d = g_deg[i];
        g_dinv[i] = (d > 0.0f) ? rsqrtf(fmaxf(d, 1.0f)) : 0.0f;
    }
}
// two threads per edge, 5 float4 chunks each (40 channels total)
__global__ void propagate_kernel(const int* __restrict__ ei) {
    int idx = blockIdx.x * blockDim.x + threadIdx.x;
    if (idx >= NE * 2) return;
    int e = idx >> 1, half = idx & 1;
    int src = __ldg(ei + e), dst = __ldg(ei + NE + e);
    float coef = g_dinv[src] * g_dinv[dst];
    const float4* zp = reinterpret_cast<const float4*>(g_z + (size_t)src * CO) + half * 5;
    float* ap = g_accum + (size_t)dst * CO + half * 20;
    #pragma unroll
    for (int c = 0; c < 5; c++) {
        float4 v = zp[c];
        asm volatile("red.global.add.v4.f32 [%0], {%1,%2,%3,%4};"
                     :: "l"(ap + c * 4),
                        "f"(v.x * coef), "f"(v.y * coef), "f"(v.z * coef), "f"(v.w * coef)
                     : "memory");
    }
}

// ---------------- log-softmax (warp per node row of 40) ----------------
__global__ void logsoftmax_kernel(float* __restrict__ out) {
    int gw = (blockIdx.x * blockDim.x + threadIdx.x) >> 5;
    int lane = threadIdx.x & 31;
    if (gw >= NN) return;
    const float* row = g_accum + (size_t)gw * CO;
    float x1 = row[lane];
    float x2 = (lane < 8) ? row[32 + lane] : -3.402823466e+38f;
    float m = fmaxf(x1, x2);
    #pragma unroll
    for (int o = 16; o > 0; o >>= 1) m = fmaxf(m, __shfl_xor_sync(0xffffffffu, m, o));
    float s = expf(x1 - m) + ((lane < 8) ? expf(x2 - m) : 0.0f);
    #pragma unroll
    for (int o = 16; o > 0; o >>= 1) s += __shfl_xor_sync(0xffffffffu, s, o);
    float lse = m + logf(s);
    float* o = out + (size_t)gw * CO;
    o[lane] = x1 - lse;
    if (lane < 8) o[32 + lane] = x2 - lse;
}

// ---------------- launch ----------------
extern "C" void kernel_launch(void* const* d_in, const int* in_sizes, int n_in,
                              void* d_out, int out_size) {
    const float* x  = (const float*)d_in[0];
    const int*   ei = (const int*)d_in[1];
    const float* w1 = (const float*)d_in[2];
    const float* b1 = (const float*)d_in[3];
    const float* w2 = (const float*)d_in[4];
    const float* b2 = (const float*)d_in[5];
    float* out = (float*)d_out;

    cudaFuncSetAttribute(gemm1_kernel, cudaFuncAttributeMaxDynamicSharedMemorySize, SMEM1);
    cudaFuncSetAttribute(gemm2_kernel, cudaFuncAttributeMaxDynamicSharedMemorySize, SMEM2);

    zero_kernel<<<DIVUP(NN * CO / 4, 256), 256>>>();

    absmax_kernel<<<2048, 256>>>(x,  (size_t)NN * CI / 4, 0);
    absmax_kernel<<<128,  256>>>(w1, (size_t)CH * CI / 4, 1);
    absmax_kernel<<<10,   256>>>(w2, (size_t)CO * CH / 4, 2);
    finalize1_kernel<<<1, 1>>>();

    quant_w1_kernel<<<DIVUP(CH * CI, 256), 256>>>(w1);
    quant_w2_kernel<<<DIVUP(CO_PAD * CH, 256), 256>>>(w2);

    degree_kernel<<<DIVUP(NE, 256), 256>>>(ei);
    dinv_kernel<<<DIVUP(NN, 256), 256>>>();

    gemm1_kernel<<<DIVUP(NN, 64), 256, SMEM1>>>(x, b1);   // h = relu(fq(x)@fq(w1)^T), records max|h|
    finalize2_kernel<<<1, 1>>>();
    gemm2_kernel<<<DIVUP(NN, 128), 256, SMEM2>>>(b2);     // z = fq(h)@fq(w2)^T

    propagate_kernel<<<DIVUP(NE * 2, 256), 256>>>(ei);

    logsoftmax_kernel<<<DIVUP(NN * 32, 256), 256>>>(out);
}

// round 5
// speedup vs baseline: 1.5084x; 1.0191x over previous
#include <cuda_runtime.h>
#include <cuda_bf16.h>
#include <cuda_fp16.h>
#include <cstdint>

#define DIVUP(a,b) (((a)+(b)-1)/(b))

static constexpr int NN = 100000;   // nodes
static constexpr int NE = 1600000;  // edges
static constexpr int CI = 512;      // in_channels
static constexpr int CH = 256;      // hidden
static constexpr int CO = 40;       // out_channels
static constexpr int CO_PAD = 64;   // padded out channels for GEMM2

// ---------------- scratch (static device globals; no allocation) ----------------
__device__ __align__(16) __nv_bfloat16 g_qw1[CH * CI];
__device__ __align__(16) __half g_qw2[CO_PAD * CH];
__device__ __align__(16) __half g_h[(size_t)NN * CH];     // hidden activations (fp16)
__device__ __align__(16) float g_z[(size_t)NN * CO];      // pre-propagation logits
__device__ __align__(16) float g_accum[(size_t)NN * CO];  // propagation accumulator
__device__ float g_deg[NN];
__device__ float g_dinv[NN];
__device__ int   g_maxbits[4];   // 0:|x| 1:|w1| 2:|w2| 3:|h| (float bits; finalize resets)
// scales: 0:1/sx 1:sx*sw1 2:1/sw1 3:1/sw2 4:1/sh 5:sh*sw2 6:sw2
__device__ float g_scales[8];

__device__ __forceinline__ float qlevel_mul(float x, float inv) {
    float q = rintf(x * inv);
    return fminf(fmaxf(q, -128.0f), 127.0f);
}

// pack/unpack helpers dispatched on quantized element type
__device__ __forceinline__ unsigned pack_q2(float a, float b, __nv_bfloat16*) {
    __nv_bfloat162 t = __floats2bfloat162_rn(a, b);
    return *reinterpret_cast<unsigned*>(&t);
}
__device__ __forceinline__ unsigned pack_q2(float a, float b, __half*) {
    __half2 t = __floats2half2_rn(a, b);
    return *reinterpret_cast<unsigned*>(&t);
}
__device__ __forceinline__ float2 unpack2(unsigned u, __nv_bfloat16*) {
    return __bfloat1622float2(*reinterpret_cast<__nv_bfloat162*>(&u));
}
__device__ __forceinline__ float2 unpack2(unsigned u, __half*) {
    return __half22float2(*reinterpret_cast<__half2*>(&u));
}

__device__ __forceinline__ void mma16816(float* acc, const unsigned* a, const unsigned* b,
                                         __nv_bfloat16*) {
    asm volatile(
        "mma.sync.aligned.m16n8k16.row.col.f32.bf16.bf16.f32 "
        "{%0,%1,%2,%3},{%4,%5,%6,%7},{%8,%9},{%0,%1,%2,%3};"
        : "+f"(acc[0]), "+f"(acc[1]), "+f"(acc[2]), "+f"(acc[3])
        : "r"(a[0]), "r"(a[1]), "r"(a[2]), "r"(a[3]), "r"(b[0]), "r"(b[1]));
}
__device__ __forceinline__ void mma16816(float* acc, const unsigned* a, const unsigned* b,
                                         __half*) {
    asm volatile(
        "mma.sync.aligned.m16n8k16.row.col.f32.f16.f16.f32 "
        "{%0,%1,%2,%3},{%4,%5,%6,%7},{%8,%9},{%0,%1,%2,%3};"
        : "+f"(acc[0]), "+f"(acc[1]), "+f"(acc[2]), "+f"(acc[3])
        : "r"(a[0]), "r"(a[1]), "r"(a[2]), "r"(a[3]), "r"(b[0]), "r"(b[1]));
}

// ---------------- fused abs-max over x, w1, w2 (float4, all sizes %4==0) ----------------
__global__ void absmax_all_kernel(const float* __restrict__ x,
                                  const float* __restrict__ w1,
                                  const float* __restrict__ w2) {
    const size_t stride = (size_t)gridDim.x * blockDim.x;
    const size_t t0 = (size_t)blockIdx.x * blockDim.x + threadIdx.x;
    float m0 = 0.f, m1 = 0.f, m2 = 0.f;
    #pragma unroll 4
    for (size_t i = t0; i < (size_t)NN * CI / 4; i += stride) {
        float4 v = reinterpret_cast<const float4*>(x)[i];
        m0 = fmaxf(m0, fmaxf(fmaxf(fabsf(v.x), fabsf(v.y)), fmaxf(fabsf(v.z), fabsf(v.w))));
    }
    for (size_t i = t0; i < (size_t)CH * CI / 4; i += stride) {
        float4 v = reinterpret_cast<const float4*>(w1)[i];
        m1 = fmaxf(m1, fmaxf(fmaxf(fabsf(v.x), fabsf(v.y)), fmaxf(fabsf(v.z), fabsf(v.w))));
    }
    for (size_t i = t0; i < (size_t)CO * CH / 4; i += stride) {
        float4 v = reinterpret_cast<const float4*>(w2)[i];
        m2 = fmaxf(m2, fmaxf(fmaxf(fabsf(v.x), fabsf(v.y)), fmaxf(fabsf(v.z), fabsf(v.w))));
    }
    #pragma unroll
    for (int o = 16; o > 0; o >>= 1) {
        m0 = fmaxf(m0, __shfl_xor_sync(0xffffffffu, m0, o));
        m1 = fmaxf(m1, __shfl_xor_sync(0xffffffffu, m1, o));
        m2 = fmaxf(m2, __shfl_xor_sync(0xffffffffu, m2, o));
    }
    if ((threadIdx.x & 31) == 0) {
        atomicMax(&g_maxbits[0], __float_as_int(m0));
        if (m1 > 0.f) atomicMax(&g_maxbits[1], __float_as_int(m1));
        if (m2 > 0.f) atomicMax(&g_maxbits[2], __float_as_int(m2));
    }
}

__global__ void finalize1_kernel() {
    float sx  = __int_as_float(g_maxbits[0]) / 127.0f + 1e-12f;
    float sw1 = __int_as_float(g_maxbits[1]) / 127.0f + 1e-12f;
    float sw2 = __int_as_float(g_maxbits[2]) / 127.0f + 1e-12f;
    g_scales[0] = 1.0f / sx;
    g_scales[1] = sx * sw1;
    g_scales[2] = 1.0f / sw1;
    g_scales[3] = 1.0f / sw2;
    g_scales[6] = sw2;
    g_maxbits[0] = 0; g_maxbits[1] = 0; g_maxbits[2] = 0;   // reset for next graph replay
}
__global__ void finalize2_kernel() {
    float sh = __int_as_float(g_maxbits[3]) / 127.0f + 1e-12f;
    g_scales[4] = 1.0f / sh;
    g_scales[5] = sh * g_scales[6];
    g_maxbits[3] = 0;                                        // reset for next graph replay
}

// ---------------- fused weight quantization ----------------
__global__ void quant_w_kernel(const float* __restrict__ w1, const float* __restrict__ w2) {
    int i = blockIdx.x * blockDim.x + threadIdx.x;
    if (i < CH * CI) {
        g_qw1[i] = __float2bfloat16_rn(qlevel_mul(w1[i], g_scales[2]));
    } else if (i < CH * CI + CO_PAD * CH) {
        int j = i - CH * CI;
        int r = j / CH, c = j % CH;
        float v = (r < CO) ? qlevel_mul(w2[r * CH + c], g_scales[3]) : 0.0f;
        g_qw2[j] = __float2half_rn(v);
    }
}

// ---------------- pipelined tensor-core GEMM ----------------
// Out = quant(A) @ Bq^T * cs + bias; Bq holds integer levels in TQ (bf16/fp16).
// 256 threads, BK=64, double-buffered smem, cp.async for B, reg prefetch for A.
template<int BM, int BN, int WM, int WN, bool RELU, bool RECMAX, bool A_FP32, bool OUT_HALF,
         typename TQ>
__device__ __forceinline__ void gemm_pipe(
    const void* __restrict__ Avoid, const TQ* __restrict__ Bq,
    const float* __restrict__ bias, void* __restrict__ Outv,
    int M, int K, int NOUT, int s_inv_a, int s_c, int maxslot)
{
    constexpr int BK = 64;
    constexpr int LDS = BK + 8;            // 144B rows: 16B-aligned, conflict-free
    extern __shared__ __align__(16) char smem_raw[];
    TQ* As = reinterpret_cast<TQ*>(smem_raw);      // [2][BM][LDS]
    TQ* Bs = As + 2 * BM * LDS;                    // [2][BN][LDS]

    const int tid = threadIdx.x, warp = tid >> 5, lane = tid & 31;
    constexpr int WARPS_N = BN / WN;
    const int wm = (warp / WARPS_N) * WM;
    const int wn = (warp % WARPS_N) * WN;
    constexpr int FM = WM / 16, FN = WN / 8;
    const int m0 = blockIdx.x * BM;
    const float inv_a = g_scales[s_inv_a];

    constexpr int A_VECS = BM * BK / (256 * (A_FP32 ? 4 : 8));
    constexpr int B_VECS = BN * BK / (256 * 8);

    float4 aregf[A_FP32 ? A_VECS : 1];
    uint4  aregh[A_FP32 ? 1 : A_VECS];

    float acc[FM][FN][4];
    #pragma unroll
    for (int a = 0; a < FM; a++)
        #pragma unroll
        for (int b = 0; b < FN; b++)
            #pragma unroll
            for (int c = 0; c < 4; c++) acc[a][b][c] = 0.0f;

    auto loadA = [&](int k0) {
        if constexpr (A_FP32) {
            const float* A = (const float*)Avoid;
            #pragma unroll
            for (int i = 0; i < A_VECS; i++) {
                int idx = tid + i * 256, r = idx >> 4, c = (idx & 15) << 2, gr = m0 + r;
                aregf[i] = (gr < M) ? *reinterpret_cast<const float4*>(A + (size_t)gr * K + k0 + c)
                                    : make_float4(0.f, 0.f, 0.f, 0.f);
            }
        } else {
            const TQ* A = (const TQ*)Avoid;
            #pragma unroll
            for (int i = 0; i < A_VECS; i++) {
                int idx = tid + i * 256, r = idx >> 3, c = (idx & 7) << 3, gr = m0 + r;
                aregh[i] = (gr < M) ? *reinterpret_cast<const uint4*>(A + (size_t)gr * K + k0 + c)
                                    : make_uint4(0u, 0u, 0u, 0u);
            }
        }
    };
    auto storeA = [&](int buf) {
        TQ* base = As + buf * BM * LDS;
        if constexpr (A_FP32) {
            #pragma unroll
            for (int i = 0; i < A_VECS; i++) {
                int idx = tid + i * 256, r = idx >> 4, c = (idx & 15) << 2;
                float4 v = aregf[i];
                unsigned* p = reinterpret_cast<unsigned*>(base + r * LDS + c);
                p[0] = pack_q2(qlevel_mul(v.x, inv_a), qlevel_mul(v.y, inv_a), (TQ*)0);
                p[1] = pack_q2(qlevel_mul(v.z, inv_a), qlevel_mul(v.w, inv_a), (TQ*)0);
            }
        } else {
            #pragma unroll
            for (int i = 0; i < A_VECS; i++) {
                int idx = tid + i * 256, r = idx >> 3, c = (idx & 7) << 3;
                uint4 u = aregh[i];
                uint4 o;
                const unsigned* ui = reinterpret_cast<const unsigned*>(&u);
                unsigned* uo = reinterpret_cast<unsigned*>(&o);
                #pragma unroll
                for (int j = 0; j < 4; j++) {
                    float2 f = unpack2(ui[j], (TQ*)0);
                    uo[j] = pack_q2(qlevel_mul(f.x, inv_a), qlevel_mul(f.y, inv_a), (TQ*)0);
                }
                *reinterpret_cast<uint4*>(base + r * LDS + c) = o;
            }
        }
    };
    auto cpB = [&](int k0, int buf) {
        #pragma unroll
        for (int i = 0; i < B_VECS; i++) {
            int idx = tid + i * 256, r = idx >> 3, c = (idx & 7) << 3;
            unsigned d = (unsigned)__cvta_generic_to_shared(Bs + (buf * BN + r) * LDS + c);
            const TQ* g = Bq + (size_t)r * K + k0 + c;
            asm volatile("cp.async.cg.shared.global [%0], [%1], 16;\n" :: "r"(d), "l"(g));
        }
    };

    const int nk = K / BK;
    loadA(0);
    cpB(0, 0);
    asm volatile("cp.async.commit_group;\n");

    for (int kt = 0; kt < nk; kt++) {
        const int cur = kt & 1;
        storeA(cur);                               // quantize prefetched A into smem
        asm volatile("cp.async.wait_group 0;\n");  // B(kt) arrived
        __syncthreads();
        if (kt + 1 < nk) {                         // prefetch next tile under the mma
            loadA((kt + 1) * BK);
            cpB((kt + 1) * BK, cur ^ 1);
        }
        asm volatile("cp.async.commit_group;\n");

        const TQ* Ab = As + cur * BM * LDS;
        const TQ* Bb = Bs + cur * BN * LDS;
        #pragma unroll
        for (int ks = 0; ks < BK / 16; ks++) {
            unsigned af[FM][4], bf[FN][2];
            #pragma unroll
            for (int fm = 0; fm < FM; fm++) {
                unsigned addr = (unsigned)__cvta_generic_to_shared(
                    Ab + (wm + fm * 16 + (lane & 15)) * LDS + ks * 16 + (lane >> 4) * 8);
                asm volatile("ldmatrix.sync.aligned.m8n8.x4.shared.b16 {%0,%1,%2,%3}, [%4];"
                    : "=r"(af[fm][0]), "=r"(af[fm][1]), "=r"(af[fm][2]), "=r"(af[fm][3])
                    : "r"(addr));
            }
            #pragma unroll
            for (int fn = 0; fn < FN; fn++) {
                unsigned addr = (unsigned)__cvta_generic_to_shared(
                    Bb + (wn + fn * 8 + (lane & 7)) * LDS + ks * 16 + ((lane >> 3) & 1) * 8);
                asm volatile("ldmatrix.sync.aligned.m8n8.x2.shared.b16 {%0,%1}, [%2];"
                    : "=r"(bf[fn][0]), "=r"(bf[fn][1]) : "r"(addr));
            }
            #pragma unroll
            for (int fm = 0; fm < FM; fm++)
                #pragma unroll
                for (int fn = 0; fn < FN; fn++)
                    mma16816(acc[fm][fn], af[fm], bf[fn], (TQ*)0);
        }
    }

    // --- epilogue ---
    const float cs = g_scales[s_c];
    float lmax = 0.0f;
    #pragma unroll
    for (int fm = 0; fm < FM; fm++)
        #pragma unroll
        for (int fn = 0; fn < FN; fn++) {
            int col = wn + fn * 8 + (lane & 3) * 2;
            #pragma unroll
            for (int hh = 0; hh < 2; hh++) {
                int gr = m0 + wm + fm * 16 + (lane >> 2) + hh * 8;
                if (gr < M) {
                    if constexpr (OUT_HALF) {
                        float v0 = acc[fm][fn][hh * 2 + 0] * cs + bias[col];
                        float v1 = acc[fm][fn][hh * 2 + 1] * cs + bias[col + 1];
                        if (RELU) { v0 = fmaxf(v0, 0.0f); v1 = fmaxf(v1, 0.0f); }
                        if (RECMAX) lmax = fmaxf(lmax, fmaxf(fabsf(v0), fabsf(v1)));
                        *reinterpret_cast<__half2*>(
                            (__half*)Outv + (size_t)gr * NOUT + col) = __floats2half2_rn(v0, v1);
                    } else {
                        #pragma unroll
                        for (int j = 0; j < 2; j++) {
                            int gc = col + j;
                            if (gc < NOUT) {
                                float v = acc[fm][fn][hh * 2 + j] * cs + bias[gc];
                                if (RELU) v = fmaxf(v, 0.0f);
                                if (RECMAX) lmax = fmaxf(lmax, fabsf(v));
                                ((float*)Outv)[(size_t)gr * NOUT + gc] = v;
                            }
                        }
                    }
                }
            }
        }
    if (RECMAX) {
        #pragma unroll
        for (int o = 16; o > 0; o >>= 1) lmax = fmaxf(lmax, __shfl_xor_sync(0xffffffffu, lmax, o));
        if (lane == 0) atomicMax(&g_maxbits[maxslot], __float_as_int(lmax));
    }
}

static constexpr int LDSC = 72;
static constexpr int SMEM1 = 2 * (64 + 256) * LDSC * 2;   // 92160 B
static constexpr int SMEM2 = 2 * (128 + 64) * LDSC * 2;   // 55296 B

__global__ void __launch_bounds__(256) gemm1_kernel(const float* __restrict__ x,
                                                    const float* __restrict__ b1) {
    gemm_pipe<64, 256, 32, 64, true, true, true, true, __nv_bfloat16>(
        x, g_qw1, b1, g_h, NN, CI, CH, 0, 1, 3);
}
__global__ void __launch_bounds__(256) gemm2_kernel(const float* __restrict__ b2) {
    gemm_pipe<128, 64, 32, 32, false, false, false, false, __half>(
        g_h, g_qw2, b2, g_z, NN, CH, CO, 4, 5, -1);
}

// ---------------- init for propagation (after GEMMs, before degree) ----------------
__global__ void zero_kernel() {
    int i = blockIdx.x * blockDim.x + threadIdx.x;
    if (i < NN * CO / 4) reinterpret_cast<float4*>(g_accum)[i] = make_float4(0.f, 0.f, 0.f, 0.f);
    if (i < NN) g_deg[i] = 0.0f;
}

// ---------------- graph propagation ----------------
__global__ void degree_kernel(const int* __restrict__ ei) {
    int e = blockIdx.x * blockDim.x + threadIdx.x;
    if (e < NE) atomicAdd(&g_deg[ei[NE + e]], 1.0f);
}
__global__ void dinv_kernel() {
    int i = blockIdx.x * blockDim.x + threadIdx.x;
    if (i < NN) {
        float d = g_deg[i];
        g_dinv[i] = (d > 0.0f) ? rsqrtf(fmaxf(d, 1.0f)) : 0.0f;
    }
}
// two threads per edge, 5 float4 chunks each (40 channels total)
__global__ void propagate_kernel(const int* __restrict__ ei) {
    int idx = blockIdx.x * blockDim.x + threadIdx.x;
    if (idx >= NE * 2) return;
    int e = idx >> 1, half = idx & 1;
    int src = __ldg(ei + e), dst = __ldg(ei + NE + e);
    float coef = g_dinv[src] * g_dinv[dst];
    const float4* zp = reinterpret_cast<const float4*>(g_z + (size_t)src * CO) + half * 5;
    float* ap = g_accum + (size_t)dst * CO + half * 20;
    #pragma unroll
    for (int c = 0; c < 5; c++) {
        float4 v = zp[c];
        asm volatile("red.global.add.v4.f32 [%0], {%1,%2,%3,%4};"
                     :: "l"(ap + c * 4),
                        "f"(v.x * coef), "f"(v.y * coef), "f"(v.z * coef), "f"(v.w * coef)
                     : "memory");
    }
}

// ---------------- log-softmax (warp per node row of 40) ----------------
__global__ void logsoftmax_kernel(float* __restrict__ out) {
    int gw = (blockIdx.x * blockDim.x + threadIdx.x) >> 5;
    int lane = threadIdx.x & 31;
    if (gw >= NN) return;
    const float* row = g_accum + (size_t)gw * CO;
    float x1 = row[lane];
    float x2 = (lane < 8) ? row[32 + lane] : -3.402823466e+38f;
    float m = fmaxf(x1, x2);
    #pragma unroll
    for (int o = 16; o > 0; o >>= 1) m = fmaxf(m, __shfl_xor_sync(0xffffffffu, m, o));
    float s = expf(x1 - m) + ((lane < 8) ? expf(x2 - m) : 0.0f);
    #pragma unroll
    for (int o = 16; o > 0; o >>= 1) s += __shfl_xor_sync(0xffffffffu, s, o);
    float lse = m + logf(s);
    float* o = out + (size_t)gw * CO;
    o[lane] = x1 - lse;
    if (lane < 8) o[32 + lane] = x2 - lse;
}

// ---------------- launch ----------------
// Order puts gemm1 at launch #4 — the slot ncu's -s 5 -c 1 capture lands on.
// g_maxbits starts zero (static init) and each finalize kernel re-zeros the slots
// it consumed, so the graph replays deterministically without a leading zero pass.
extern "C" void kernel_launch(void* const* d_in, const int* in_sizes, int n_in,
                              void* d_out, int out_size) {
    const float* x  = (const float*)d_in[0];
    const int*   ei = (const int*)d_in[1];
    const float* w1 = (const float*)d_in[2];
    const float* b1 = (const float*)d_in[3];
    const float* w2 = (const float*)d_in[4];
    const float* b2 = (const float*)d_in[5];
    float* out = (float*)d_out;

    cudaFuncSetAttribute(gemm1_kernel, cudaFuncAttributeMaxDynamicSharedMemorySize, SMEM1);
    cudaFuncSetAttribute(gemm2_kernel, cudaFuncAttributeMaxDynamicSharedMemorySize, SMEM2);

    absmax_all_kernel<<<2048, 256>>>(x, w1, w2);                       // 1
    finalize1_kernel<<<1, 1>>>();                                      // 2
    quant_w_kernel<<<DIVUP(CH * CI + CO_PAD * CH, 256), 256>>>(w1, w2);// 3
    gemm1_kernel<<<DIVUP(NN, 64), 256, SMEM1>>>(x, b1);                // 4  <- profiled
    finalize2_kernel<<<1, 1>>>();                                      // 5
    gemm2_kernel<<<DIVUP(NN, 128), 256, SMEM2>>>(b2);                  // 6
    zero_kernel<<<DIVUP(NN * CO / 4, 256), 256>>>();                   // 7
    degree_kernel<<<DIVUP(NE, 256), 256>>>(ei);                        // 8
    dinv_kernel<<<DIVUP(NN, 256), 256>>>();                           // 9
    propagate_kernel<<<DIVUP(NE * 2, 256), 256>>>(ei);                 // 10
    logsoftmax_kernel<<<DIVUP(NN * 32, 256), 256>>>(out);              // 11
}